// round 13
// baseline (speedup 1.0000x reference)
#include <cuda_runtime.h>
#include <math.h>

#define BATCH  32
#define NPTS   131072
#define TPB    256
#define N4     (NPTS / 4)            // 32768 float4 per stream per batch
#define CHUNKS (N4 / TPB)            // 128 blocks per batch, 1 float4/thread/stream

// per-(batch,chunk) 16 partial sums:
// [0]=W, [1..3]=Sum(w*xs), [4..6]=Sum(w*xt), [7..15]=Sum(w*xs_d*xt_e)
__device__ float g_part[BATCH][CHUNKS][16];

__global__ void __launch_bounds__(TPB) reduce_kernel(
        const float* __restrict__ xyz_s,
        const float* __restrict__ weighted_t,
        const float* __restrict__ weights,
        const float* __restrict__ label) {
    const int b = blockIdx.y;
    const int i = blockIdx.x * TPB + threadIdx.x;   // float4 index within batch
    const size_t base3 = (size_t)b * 3 * NPTS;
    const size_t base1 = (size_t)b * NPTS;

    // 8 independent 128-bit streaming loads (evict-first; data is read once)
    const float4 X0 = __ldcs(&((const float4*)(xyz_s + base3))[i]);
    const float4 X1 = __ldcs(&((const float4*)(xyz_s + base3 + NPTS))[i]);
    const float4 X2 = __ldcs(&((const float4*)(xyz_s + base3 + 2 * NPTS))[i]);
    const float4 T0 = __ldcs(&((const float4*)(weighted_t + base3))[i]);
    const float4 T1 = __ldcs(&((const float4*)(weighted_t + base3 + NPTS))[i]);
    const float4 T2 = __ldcs(&((const float4*)(weighted_t + base3 + 2 * NPTS))[i]);
    const float4 Wv = __ldcs(&((const float4*)(weights + base1))[i]);
    const float4 Lv = __ldcs(&((const float4*)(label + base1))[i]);

    float a[16];
#pragma unroll
    for (int k = 0; k < 16; k++) a[k] = 0.0f;

#define LANE(c)                                                        \
    {                                                                  \
        float w  = Wv.c * fabsf(Lv.c - 1.0f);                          \
        float x0 = X0.c, x1 = X1.c, x2 = X2.c;                         \
        float t0 = T0.c, t1 = T1.c, t2 = T2.c;                         \
        a[0] += w;                                                     \
        float w0 = w * x0, w1 = w * x1, w2 = w * x2;                   \
        a[1] += w0; a[2] += w1; a[3] += w2;                            \
        a[4] += w * t0; a[5] += w * t1; a[6] += w * t2;                \
        a[7]  += w0 * t0; a[8]  += w0 * t1; a[9]  += w0 * t2;          \
        a[10] += w1 * t0; a[11] += w1 * t1; a[12] += w1 * t2;          \
        a[13] += w2 * t0; a[14] += w2 * t1; a[15] += w2 * t2;          \
    }
    LANE(x) LANE(y) LANE(z) LANE(w)
#undef LANE

    // smem-transpose block reduce: thread stores 16 accums; warp w reduces
    // accumulators 2w and 2w+1 (TPB=256 -> 8 warps, 16 accumulators)
    __shared__ float sm[16][TPB];
#pragma unroll
    for (int k = 0; k < 16; k++) sm[k][threadIdx.x] = a[k];
    __syncthreads();

    const int w = threadIdx.x >> 5;
    const int l = threadIdx.x & 31;
#pragma unroll
    for (int kk = 0; kk < 2; kk++) {
        const int k = 2 * w + kk;
        const float4 p0 = *(const float4*)&sm[k][l * 8];
        const float4 p1 = *(const float4*)&sm[k][l * 8 + 4];
        float s = ((p0.x + p0.y) + (p0.z + p0.w))
                + ((p1.x + p1.y) + (p1.z + p1.w));
#pragma unroll
        for (int off = 16; off > 0; off >>= 1)
            s += __shfl_down_sync(0xffffffffu, s, off);
        if (l == 0) g_part[b][blockIdx.x][k] = s;
    }
}

// sqrt for x >= 0 via single MUFU (guarded against 0)
__device__ __forceinline__ float fsqrt_fast(float x) {
    x = fmaxf(x, 1e-30f);
    return x * rsqrtf(x);
}

// det of 3x3 minor of 4x4 B, removing row r and col c
__device__ __forceinline__ float minor3(const float B[4][4], int r, int c) {
    int rr[3], cc[3];
    int n = 0;
    for (int k = 0; k < 4; k++) if (k != r) rr[n++] = k;
    n = 0;
    for (int k = 0; k < 4; k++) if (k != c) cc[n++] = k;
    const float a00 = B[rr[0]][cc[0]], a01 = B[rr[0]][cc[1]], a02 = B[rr[0]][cc[2]];
    const float a10 = B[rr[1]][cc[0]], a11 = B[rr[1]][cc[1]], a12 = B[rr[1]][cc[2]];
    const float a20 = B[rr[2]][cc[0]], a21 = B[rr[2]][cc[1]], a22 = B[rr[2]][cc[2]];
    return a00 * (a11 * a22 - a12 * a21)
         - a01 * (a10 * a22 - a12 * a20)
         + a02 * (a10 * a21 - a11 * a20);
}

__device__ void solve_batch(const float S[16], float* __restrict__ out, int b) {
    const float W = S[0];
    const float inv_denom = __fdividef(1.0f, W + 1e-6f);
    float cs[3], ct[3];
#pragma unroll
    for (int d = 0; d < 3; d++) {
        cs[d] = S[1 + d] * inv_denom;
        ct[d] = S[4 + d] * inv_denom;
    }

    // cov = M/denom - cs*ct^T * (2 - W/denom)
    const float f = 2.0f - W * inv_denom;
    float cov[3][3];
#pragma unroll
    for (int d = 0; d < 3; d++)
#pragma unroll
        for (int e = 0; e < 3; e++)
            cov[d][e] = S[7 + d * 3 + e] * inv_denom - cs[d] * ct[e] * f;

    const float Sxx = cov[0][0], Sxy = cov[0][1], Sxz = cov[0][2];
    const float Syx = cov[1][0], Syy = cov[1][1], Syz = cov[1][2];
    const float Szx = cov[2][0], Szy = cov[2][1], Szz = cov[2][2];

    // Horn/Besl-McKay 4x4 quaternion matrix (trace = 0)
    float N[4][4];
    N[0][0] = Sxx + Syy + Szz;
    N[0][1] = Syz - Szy;  N[0][2] = Szx - Sxz;  N[0][3] = Sxy - Syx;
    N[1][1] = Sxx - Syy - Szz;
    N[1][2] = Sxy + Syx;  N[1][3] = Szx + Sxz;
    N[2][2] = -Sxx + Syy - Szz;
    N[2][3] = Syz + Szy;
    N[3][3] = -Sxx - Syy + Szz;
    N[1][0] = N[0][1]; N[2][0] = N[0][2]; N[3][0] = N[0][3];
    N[2][1] = N[1][2]; N[3][1] = N[1][3]; N[3][2] = N[2][3];

    // characteristic quartic: lam^4 + c2 lam^2 + c1 lam + c0  (tr(N)=0)
    float tr2 = 0.0f;
#pragma unroll
    for (int i = 0; i < 4; i++)
#pragma unroll
        for (int j = 0; j < 4; j++) tr2 += N[i][j] * N[i][j];
    const float c2 = -0.5f * tr2;

    // tr(N^3) via N2 = N*N, then sum N2[i][j]*N[i][j] (N symmetric)
    float N2[4][4];
#pragma unroll
    for (int i = 0; i < 4; i++)
#pragma unroll
        for (int j = 0; j < 4; j++) {
            float s = 0.0f;
#pragma unroll
            for (int k = 0; k < 4; k++) s += N[i][k] * N[k][j];
            N2[i][j] = s;
        }
    float tr3 = 0.0f;
#pragma unroll
    for (int i = 0; i < 4; i++)
#pragma unroll
        for (int j = 0; j < 4; j++) tr3 += N2[i][j] * N[i][j];
    const float c1 = -tr3 * (1.0f / 3.0f);

    // c0 = det(N): Laplace along row 0
    float c0 = 0.0f;
    {
        float sgn = 1.0f;
#pragma unroll
        for (int j = 0; j < 4; j++) {
            c0 += sgn * N[0][j] * minor3(N, 0, j);
            sgn = -sgn;
        }
    }

    float R[3][3] = {{1, 0, 0}, {0, 1, 0}, {0, 0, 1}};

    if (tr2 > 1e-30f) {
        // Newton for largest root, starting above it (monotone, convex region)
        float lam = fsqrt_fast(tr2);
#pragma unroll
        for (int it = 0; it < 10; it++) {
            const float l2 = lam * lam;
            const float p  = ((l2 + c2) * lam + c1) * lam + c0;
            const float dp = (4.0f * l2 + 2.0f * c2) * lam + c1;
            lam -= __fdividef(p, dp);
        }

        // eigenvector = largest-norm adjugate row of B = N - lam I
        float B[4][4];
#pragma unroll
        for (int i = 0; i < 4; i++)
#pragma unroll
            for (int j = 0; j < 4; j++)
                B[i][j] = N[i][j] - (i == j ? lam : 0.0f);

        float q[4] = {1, 0, 0, 0};
        float best = 0.0f;
#pragma unroll
        for (int r = 0; r < 4; r++) {
            float v[4];
#pragma unroll
            for (int i = 0; i < 4; i++) {
                const float sgn = (((r + i) & 1) == 0) ? 1.0f : -1.0f;
                v[i] = sgn * minor3(B, r, i);
            }
            const float nrm = v[0]*v[0] + v[1]*v[1] + v[2]*v[2] + v[3]*v[3];
            if (nrm > best) {
                best = nrm;
                q[0] = v[0]; q[1] = v[1]; q[2] = v[2]; q[3] = v[3];
            }
        }

        if (best > 1e-30f) {
            const float inv = __fdividef(1.0f, q[0]*q[0] + q[1]*q[1] + q[2]*q[2] + q[3]*q[3]);
            const float w = q[0], x = q[1], y = q[2], z = q[3];
            R[0][0] = (w*w + x*x - y*y - z*z) * inv;
            R[0][1] = 2.0f * (x*y - w*z) * inv;
            R[0][2] = 2.0f * (x*z + w*y) * inv;
            R[1][0] = 2.0f * (x*y + w*z) * inv;
            R[1][1] = (w*w - x*x + y*y - z*z) * inv;
            R[1][2] = 2.0f * (y*z - w*x) * inv;
            R[2][0] = 2.0f * (x*z - w*y) * inv;
            R[2][1] = 2.0f * (y*z + w*x) * inv;
            R[2][2] = (w*w - x*x - y*y + z*z) * inv;
        }
    }

    float tr[3];
#pragma unroll
    for (int r = 0; r < 3; r++)
        tr[r] = -(R[r][0] * cs[0] + R[r][1] * cs[1] + R[r][2] * cs[2]) + ct[r];

#pragma unroll
    for (int r = 0; r < 3; r++)
#pragma unroll
        for (int c = 0; c < 3; c++)
            out[b * 9 + r * 3 + c] = R[r][c];
#pragma unroll
    for (int r = 0; r < 3; r++)
        out[BATCH * 9 + b * 3 + r] = tr[r];
}

// one warp per batch: lane l sums chunks l, l+32, l+64, l+96; shfl-reduce; lane 0 solves
__global__ void __launch_bounds__(32) solve_kernel(float* __restrict__ out) {
    const int b = blockIdx.x;
    const int l = threadIdx.x;

    float a[16];
    {
        const float4* r0 = (const float4*)g_part[b][l];
        const float4* r1 = (const float4*)g_part[b][l + 32];
        const float4* r2 = (const float4*)g_part[b][l + 64];
        const float4* r3 = (const float4*)g_part[b][l + 96];
#pragma unroll
        for (int v = 0; v < 4; v++) {
            const float4 p0 = r0[v];
            const float4 p1 = r1[v];
            const float4 p2 = r2[v];
            const float4 p3 = r3[v];
            a[v * 4 + 0] = (p0.x + p1.x) + (p2.x + p3.x);
            a[v * 4 + 1] = (p0.y + p1.y) + (p2.y + p3.y);
            a[v * 4 + 2] = (p0.z + p1.z) + (p2.z + p3.z);
            a[v * 4 + 3] = (p0.w + p1.w) + (p2.w + p3.w);
        }
    }

#pragma unroll
    for (int k = 0; k < 16; k++) {
#pragma unroll
        for (int off = 16; off > 0; off >>= 1)
            a[k] += __shfl_down_sync(0xffffffffu, a[k], off);
    }

    if (l == 0)
        solve_batch(a, out, b);
}

extern "C" void kernel_launch(void* const* d_in, const int* in_sizes, int n_in,
                              void* d_out, int out_size) {
    const float* xyz_s      = (const float*)d_in[0];
    const float* weighted_t = (const float*)d_in[1];
    const float* weights    = (const float*)d_in[2];
    const float* label      = (const float*)d_in[3];
    float* out = (float*)d_out;

    dim3 grid(CHUNKS, BATCH);
    reduce_kernel<<<grid, TPB>>>(xyz_s, weighted_t, weights, label);
    solve_kernel<<<BATCH, 32>>>(out);
}

// round 14
// speedup vs baseline: 1.0119x; 1.0119x over previous
#include <cuda_runtime.h>
#include <math.h>

#define BATCH  32
#define NPTS   131072
#define TPB    256
#define N4     (NPTS / 4)            // 32768 float4 per stream per batch
#define CHUNKS (N4 / TPB)            // 128 blocks per batch, 1 float4/thread/stream

// per-(batch,chunk) 16 partial sums:
// [0]=W, [1..3]=Sum(w*xs), [4..6]=Sum(w*xt), [7..15]=Sum(w*xs_d*xt_e)
__device__ float g_part[BATCH][CHUNKS][16];

__global__ void __launch_bounds__(TPB) reduce_kernel(
        const float* __restrict__ xyz_s,
        const float* __restrict__ weighted_t,
        const float* __restrict__ weights,
        const float* __restrict__ label) {
    const int b = blockIdx.y;
    const int i = blockIdx.x * TPB + threadIdx.x;   // float4 index within batch
    const size_t base3 = (size_t)b * 3 * NPTS;
    const size_t base1 = (size_t)b * NPTS;

    // 8 independent 128-bit streaming loads (evict-first; data is read once)
    const float4 X0 = __ldcs(&((const float4*)(xyz_s + base3))[i]);
    const float4 X1 = __ldcs(&((const float4*)(xyz_s + base3 + NPTS))[i]);
    const float4 X2 = __ldcs(&((const float4*)(xyz_s + base3 + 2 * NPTS))[i]);
    const float4 T0 = __ldcs(&((const float4*)(weighted_t + base3))[i]);
    const float4 T1 = __ldcs(&((const float4*)(weighted_t + base3 + NPTS))[i]);
    const float4 T2 = __ldcs(&((const float4*)(weighted_t + base3 + 2 * NPTS))[i]);
    const float4 Wv = __ldcs(&((const float4*)(weights + base1))[i]);
    const float4 Lv = __ldcs(&((const float4*)(label + base1))[i]);

    float a[16];
#pragma unroll
    for (int k = 0; k < 16; k++) a[k] = 0.0f;

#define LANE(c)                                                        \
    {                                                                  \
        float w  = Wv.c * fabsf(Lv.c - 1.0f);                          \
        float x0 = X0.c, x1 = X1.c, x2 = X2.c;                         \
        float t0 = T0.c, t1 = T1.c, t2 = T2.c;                         \
        a[0] += w;                                                     \
        float w0 = w * x0, w1 = w * x1, w2 = w * x2;                   \
        a[1] += w0; a[2] += w1; a[3] += w2;                            \
        a[4] += w * t0; a[5] += w * t1; a[6] += w * t2;                \
        a[7]  += w0 * t0; a[8]  += w0 * t1; a[9]  += w0 * t2;          \
        a[10] += w1 * t0; a[11] += w1 * t1; a[12] += w1 * t2;          \
        a[13] += w2 * t0; a[14] += w2 * t1; a[15] += w2 * t2;          \
    }
    LANE(x) LANE(y) LANE(z) LANE(w)
#undef LANE

    // smem-transpose block reduce: thread stores 16 accums; warp w reduces
    // accumulators 2w and 2w+1 (TPB=256 -> 8 warps, 16 accumulators)
    __shared__ float sm[16][TPB];
#pragma unroll
    for (int k = 0; k < 16; k++) sm[k][threadIdx.x] = a[k];
    __syncthreads();

    const int w = threadIdx.x >> 5;
    const int l = threadIdx.x & 31;
#pragma unroll
    for (int kk = 0; kk < 2; kk++) {
        const int k = 2 * w + kk;
        const float4 p0 = *(const float4*)&sm[k][l * 8];
        const float4 p1 = *(const float4*)&sm[k][l * 8 + 4];
        float s = ((p0.x + p0.y) + (p0.z + p0.w))
                + ((p1.x + p1.y) + (p1.z + p1.w));
#pragma unroll
        for (int off = 16; off > 0; off >>= 1)
            s += __shfl_down_sync(0xffffffffu, s, off);
        if (l == 0) g_part[b][blockIdx.x][k] = s;
    }

    // PDL: signal that this block's output is committed; dependent grid may launch
    asm volatile("griddepcontrol.launch_dependents;");
}

// sqrt for x >= 0 via single MUFU (guarded against 0)
__device__ __forceinline__ float fsqrt_fast(float x) {
    x = fmaxf(x, 1e-30f);
    return x * rsqrtf(x);
}

// det of 3x3 minor of 4x4 B, removing row r and col c
__device__ __forceinline__ float minor3(const float B[4][4], int r, int c) {
    int rr[3], cc[3];
    int n = 0;
    for (int k = 0; k < 4; k++) if (k != r) rr[n++] = k;
    n = 0;
    for (int k = 0; k < 4; k++) if (k != c) cc[n++] = k;
    const float a00 = B[rr[0]][cc[0]], a01 = B[rr[0]][cc[1]], a02 = B[rr[0]][cc[2]];
    const float a10 = B[rr[1]][cc[0]], a11 = B[rr[1]][cc[1]], a12 = B[rr[1]][cc[2]];
    const float a20 = B[rr[2]][cc[0]], a21 = B[rr[2]][cc[1]], a22 = B[rr[2]][cc[2]];
    return a00 * (a11 * a22 - a12 * a21)
         - a01 * (a10 * a22 - a12 * a20)
         + a02 * (a10 * a21 - a11 * a20);
}

__device__ void solve_batch(const float S[16], float* __restrict__ out, int b) {
    const float W = S[0];
    const float inv_denom = __fdividef(1.0f, W + 1e-6f);
    float cs[3], ct[3];
#pragma unroll
    for (int d = 0; d < 3; d++) {
        cs[d] = S[1 + d] * inv_denom;
        ct[d] = S[4 + d] * inv_denom;
    }

    // cov = M/denom - cs*ct^T * (2 - W/denom)
    const float f = 2.0f - W * inv_denom;
    float cov[3][3];
#pragma unroll
    for (int d = 0; d < 3; d++)
#pragma unroll
        for (int e = 0; e < 3; e++)
            cov[d][e] = S[7 + d * 3 + e] * inv_denom - cs[d] * ct[e] * f;

    const float Sxx = cov[0][0], Sxy = cov[0][1], Sxz = cov[0][2];
    const float Syx = cov[1][0], Syy = cov[1][1], Syz = cov[1][2];
    const float Szx = cov[2][0], Szy = cov[2][1], Szz = cov[2][2];

    // Horn/Besl-McKay 4x4 quaternion matrix (trace = 0)
    float N[4][4];
    N[0][0] = Sxx + Syy + Szz;
    N[0][1] = Syz - Szy;  N[0][2] = Szx - Sxz;  N[0][3] = Sxy - Syx;
    N[1][1] = Sxx - Syy - Szz;
    N[1][2] = Sxy + Syx;  N[1][3] = Szx + Sxz;
    N[2][2] = -Sxx + Syy - Szz;
    N[2][3] = Syz + Szy;
    N[3][3] = -Sxx - Syy + Szz;
    N[1][0] = N[0][1]; N[2][0] = N[0][2]; N[3][0] = N[0][3];
    N[2][1] = N[1][2]; N[3][1] = N[1][3]; N[3][2] = N[2][3];

    // characteristic quartic: lam^4 + c2 lam^2 + c1 lam + c0  (tr(N)=0)
    float tr2 = 0.0f;
#pragma unroll
    for (int i = 0; i < 4; i++)
#pragma unroll
        for (int j = 0; j < 4; j++) tr2 += N[i][j] * N[i][j];
    const float c2 = -0.5f * tr2;

    // tr(N^3) via N2 = N*N, then sum N2[i][j]*N[i][j] (N symmetric)
    float N2[4][4];
#pragma unroll
    for (int i = 0; i < 4; i++)
#pragma unroll
        for (int j = 0; j < 4; j++) {
            float s = 0.0f;
#pragma unroll
            for (int k = 0; k < 4; k++) s += N[i][k] * N[k][j];
            N2[i][j] = s;
        }
    float tr3 = 0.0f;
#pragma unroll
    for (int i = 0; i < 4; i++)
#pragma unroll
        for (int j = 0; j < 4; j++) tr3 += N2[i][j] * N[i][j];
    const float c1 = -tr3 * (1.0f / 3.0f);

    // c0 = det(N): Laplace along row 0
    float c0 = 0.0f;
    {
        float sgn = 1.0f;
#pragma unroll
        for (int j = 0; j < 4; j++) {
            c0 += sgn * N[0][j] * minor3(N, 0, j);
            sgn = -sgn;
        }
    }

    float R[3][3] = {{1, 0, 0}, {0, 1, 0}, {0, 0, 1}};

    if (tr2 > 1e-30f) {
        // Newton for largest root, starting above it (monotone, convex region)
        float lam = fsqrt_fast(tr2);
#pragma unroll
        for (int it = 0; it < 10; it++) {
            const float l2 = lam * lam;
            const float p  = ((l2 + c2) * lam + c1) * lam + c0;
            const float dp = (4.0f * l2 + 2.0f * c2) * lam + c1;
            lam -= __fdividef(p, dp);
        }

        // eigenvector = largest-norm adjugate row of B = N - lam I
        float B[4][4];
#pragma unroll
        for (int i = 0; i < 4; i++)
#pragma unroll
            for (int j = 0; j < 4; j++)
                B[i][j] = N[i][j] - (i == j ? lam : 0.0f);

        float q[4] = {1, 0, 0, 0};
        float best = 0.0f;
#pragma unroll
        for (int r = 0; r < 4; r++) {
            float v[4];
#pragma unroll
            for (int i = 0; i < 4; i++) {
                const float sgn = (((r + i) & 1) == 0) ? 1.0f : -1.0f;
                v[i] = sgn * minor3(B, r, i);
            }
            const float nrm = v[0]*v[0] + v[1]*v[1] + v[2]*v[2] + v[3]*v[3];
            if (nrm > best) {
                best = nrm;
                q[0] = v[0]; q[1] = v[1]; q[2] = v[2]; q[3] = v[3];
            }
        }

        if (best > 1e-30f) {
            const float inv = __fdividef(1.0f, q[0]*q[0] + q[1]*q[1] + q[2]*q[2] + q[3]*q[3]);
            const float w = q[0], x = q[1], y = q[2], z = q[3];
            R[0][0] = (w*w + x*x - y*y - z*z) * inv;
            R[0][1] = 2.0f * (x*y - w*z) * inv;
            R[0][2] = 2.0f * (x*z + w*y) * inv;
            R[1][0] = 2.0f * (x*y + w*z) * inv;
            R[1][1] = (w*w - x*x + y*y - z*z) * inv;
            R[1][2] = 2.0f * (y*z - w*x) * inv;
            R[2][0] = 2.0f * (x*z - w*y) * inv;
            R[2][1] = 2.0f * (y*z + w*x) * inv;
            R[2][2] = (w*w - x*x - y*y + z*z) * inv;
        }
    }

    float tr[3];
#pragma unroll
    for (int r = 0; r < 3; r++)
        tr[r] = -(R[r][0] * cs[0] + R[r][1] * cs[1] + R[r][2] * cs[2]) + ct[r];

#pragma unroll
    for (int r = 0; r < 3; r++)
#pragma unroll
        for (int c = 0; c < 3; c++)
            out[b * 9 + r * 3 + c] = R[r][c];
#pragma unroll
    for (int r = 0; r < 3; r++)
        out[BATCH * 9 + b * 3 + r] = tr[r];
}

// one warp per batch: lane l sums chunks l, l+32, l+64, l+96; shfl-reduce; lane 0 solves
__global__ void __launch_bounds__(32) solve_kernel(float* __restrict__ out) {
    // PDL: wait until all reduce blocks have committed their partials
    asm volatile("griddepcontrol.wait;");

    const int b = blockIdx.x;
    const int l = threadIdx.x;

    float a[16];
    {
        const float4* r0 = (const float4*)g_part[b][l];
        const float4* r1 = (const float4*)g_part[b][l + 32];
        const float4* r2 = (const float4*)g_part[b][l + 64];
        const float4* r3 = (const float4*)g_part[b][l + 96];
#pragma unroll
        for (int v = 0; v < 4; v++) {
            const float4 p0 = r0[v];
            const float4 p1 = r1[v];
            const float4 p2 = r2[v];
            const float4 p3 = r3[v];
            a[v * 4 + 0] = (p0.x + p1.x) + (p2.x + p3.x);
            a[v * 4 + 1] = (p0.y + p1.y) + (p2.y + p3.y);
            a[v * 4 + 2] = (p0.z + p1.z) + (p2.z + p3.z);
            a[v * 4 + 3] = (p0.w + p1.w) + (p2.w + p3.w);
        }
    }

#pragma unroll
    for (int k = 0; k < 16; k++) {
#pragma unroll
        for (int off = 16; off > 0; off >>= 1)
            a[k] += __shfl_down_sync(0xffffffffu, a[k], off);
    }

    if (l == 0)
        solve_batch(a, out, b);
}

extern "C" void kernel_launch(void* const* d_in, const int* in_sizes, int n_in,
                              void* d_out, int out_size) {
    const float* xyz_s      = (const float*)d_in[0];
    const float* weighted_t = (const float*)d_in[1];
    const float* weights    = (const float*)d_in[2];
    const float* label      = (const float*)d_in[3];
    float* out = (float*)d_out;

    dim3 grid(CHUNKS, BATCH);
    reduce_kernel<<<grid, TPB>>>(xyz_s, weighted_t, weights, label);

    // secondary kernel with programmatic dependent launch: front-end launches it
    // while reduce drains; griddepcontrol.wait provides the data dependency
    cudaLaunchConfig_t cfg = {};
    cfg.gridDim = dim3(BATCH);
    cfg.blockDim = dim3(32);
    cfg.dynamicSmemBytes = 0;
    cfg.stream = 0;
    cudaLaunchAttribute attrs[1];
    attrs[0].id = cudaLaunchAttributeProgrammaticStreamSerialization;
    attrs[0].val.programmaticStreamSerializationAllowed = 1;
    cfg.attrs = attrs;
    cfg.numAttrs = 1;
    cudaLaunchKernelEx(&cfg, solve_kernel, out);
}